// round 11
// baseline (speedup 1.0000x reference)
#include <cuda_runtime.h>
#include <cuda_bf16.h>
#include <cstdint>

// Grid_nd_sample: bilinear interpolation gather — cp.async pipelined.
// in_tensor: (B=16, H=128, W=128, C=256) fp32
// indices:   (B=16, P=8192, 2) fp32  -- coord0 = H axis, coord1 = W axis
// out:       (B, P, C) fp32
//
// R9 structure (best known: 61.1us) + cleanups:
//  - 64 points/block (16 iters): half the prologue/drain overhead of R9.
//  - h1=h0+1, w1=w0+1 (exact: when coord is integer, mu=0 makes the lerp
//    return p1 bitwise; +1 row always in bounds since coords < 127).
//  - rows issued as (h0,w0),(h0,w1),(h1,w0),(h1,w1): consecutive cp.asyncs
//    form contiguous 2KB runs (w1=w0+1) for DRAM row-buffer friendliness.
// DRAM traffic is compulsory (~210MB unique reads + 128MB writes); kernel sits
// near the ~75% DRAM-efficiency ceiling for this access pattern.

static constexpr int B = 16;
static constexpr int H = 128;
static constexpr int W = 128;
static constexpr int C = 256;
static constexpr int P = 8192;
static constexpr int CHUNKS = C / 4;               // 64 float4 per pixel row
static constexpr int ITERS = 16;                   // pipeline iterations
static constexpr int PPB   = ITERS * 4;            // 64 points per block
static constexpr int NBLOCKS = B * P / PPB;        // 2048

__device__ __forceinline__ void cp16(uint32_t dst_smem, const void* src_gmem) {
    asm volatile("cp.async.cg.shared.global [%0], [%1], 16;"
                 :: "r"(dst_smem), "l"(src_gmem));
}
#define CP_COMMIT() asm volatile("cp.async.commit_group;" ::: "memory")
#define CP_WAIT1()  asm volatile("cp.async.wait_group 1;" ::: "memory")
#define CP_WAIT0()  asm volatile("cp.async.wait_group 0;" ::: "memory")

__global__ __launch_bounds__(256, 6)
void grid_nd_sample_kernel(const float* __restrict__ in_tensor,
                           const float2* __restrict__ indices,
                           float4* __restrict__ out)
{
    // [stage parity][point-slot][row][chunk] : 2*4*4*64*16B = 32KB
    __shared__ float4 buf[2][4][4][CHUNKS];
    __shared__ float2 sidx[PPB];

    const unsigned tid   = threadIdx.x;
    const unsigned wid   = tid >> 5;
    const unsigned lane  = tid & 31;
    const unsigned pt4   = wid >> 1;          // point slot 0..3 within a stage
    const unsigned hf    = wid & 1;           // which half of C this warp owns
    const unsigned chunk = hf * 32 + lane;    // float4 chunk 0..63
    const unsigned pbase = blockIdx.x * PPB;

    // Stage the block's 64 indices (one coalesced 512B load).
    if (tid < PPB)
        sidx[tid] = __ldg(&indices[pbase + tid]);
    __syncthreads();

    const float4* base = (const float4*)in_tensor;

    auto issue = [&](int it) {
        int lp = it * 4 + (int)pt4;
        unsigned pidx = pbase + lp;
        unsigned b = pidx >> 13;              // P = 8192 = 2^13
        float2 ind = sidx[lp];
        int h0 = (int)floorf(ind.x);
        int w0 = (int)floorf(ind.y);
        unsigned boff = b * (H * W * CHUNKS);
        unsigned r0 = boff + (h0 * W + w0) * CHUNKS + chunk;   // (h0,w0)
        // (h0,w1)=r0+CHUNKS, (h1,w0)=r0+W*CHUNKS, (h1,w1)=r0+(W+1)*CHUNKS
        uint32_t d = (uint32_t)__cvta_generic_to_shared(&buf[it & 1][pt4][0][chunk]);
        const uint32_t ROWB = CHUNKS * 16;    // 1024B per row in buf
        // buf rows: [0]=p1(h0,w0) [1]=p2(h1,w0) [2]=p3(h0,w1) [3]=p4(h1,w1)
        // issue order pairs contiguous 2KB gmem runs: p1,p3 then p2,p4.
        cp16(d + 0 * ROWB, &base[r0]);
        cp16(d + 2 * ROWB, &base[r0 + CHUNKS]);
        cp16(d + 1 * ROWB, &base[r0 + W * CHUNKS]);
        cp16(d + 3 * ROWB, &base[r0 + (W + 1) * CHUNKS]);
    };

    // Prologue: fill both stages.
    issue(0); CP_COMMIT();
    issue(1); CP_COMMIT();

#pragma unroll
    for (int it = 0; it < ITERS; ++it) {
        if (it < ITERS - 1) { CP_WAIT1(); } else { CP_WAIT0(); }

        int lp = it * 4 + (int)pt4;
        unsigned pidx = pbase + lp;
        float2 ind = sidx[lp];
        float mu_h = ind.x - floorf(ind.x);
        float mu_w = ind.y - floorf(ind.y);

        float4 p1 = buf[it & 1][pt4][0][chunk];
        float4 p2 = buf[it & 1][pt4][1][chunk];
        float4 p3 = buf[it & 1][pt4][2][chunk];
        float4 p4 = buf[it & 1][pt4][3][chunk];

        float4 o;
        {
            float a = fmaf(mu_h, p2.x - p1.x, p1.x);
            float c = fmaf(mu_h, p4.x - p3.x, p3.x);
            o.x = fmaf(mu_w, c - a, a);
        }
        {
            float a = fmaf(mu_h, p2.y - p1.y, p1.y);
            float c = fmaf(mu_h, p4.y - p3.y, p3.y);
            o.y = fmaf(mu_w, c - a, a);
        }
        {
            float a = fmaf(mu_h, p2.z - p1.z, p1.z);
            float c = fmaf(mu_h, p4.z - p3.z, p3.z);
            o.z = fmaf(mu_w, c - a, a);
        }
        {
            float a = fmaf(mu_h, p2.w - p1.w, p1.w);
            float c = fmaf(mu_h, p4.w - p3.w, p3.w);
            o.w = fmaf(mu_w, c - a, a);
        }

        __stcs(&out[pidx * (unsigned)CHUNKS + chunk], o);

        if (it + 2 < ITERS) { issue(it + 2); CP_COMMIT(); }
    }
}

extern "C" void kernel_launch(void* const* d_in, const int* in_sizes, int n_in,
                              void* d_out, int out_size)
{
    const float*  in_tensor = (const float*)d_in[0];
    const float2* indices   = (const float2*)d_in[1];
    float4*       out       = (float4*)d_out;

    grid_nd_sample_kernel<<<NBLOCKS, 256>>>(in_tensor, indices, out);
}

// round 12
// speedup vs baseline: 1.1561x; 1.1561x over previous
#include <cuda_runtime.h>
#include <cuda_bf16.h>
#include <cstdint>

// Grid_nd_sample: bilinear interpolation gather — cp.async pipelined.
// in_tensor: (B=16, H=128, W=128, C=256) fp32
// indices:   (B=16, P=8192, 2) fp32  -- coord0 = H axis, coord1 = W axis
// out:       (B, P, C) fp32
//
// R9 structure (best known): 32 points/block, grid=4096, 2-stage cp.async
// pipeline, 6 blocks/SM. CRITICAL: 32 pts/block keeps the concurrent wave's
// batch footprint at ~4 images (64MB) < 126MB L2; 64 pts/block spans ~8
// images (128MB) and thrashes L2 (+50MB DRAM traffic, measured R11).
// Micro-opts vs R9: h1=h0+1/w1=w0+1 (bitwise-exact; mu=0 when coord is
// integer), single-base address math, cp.asyncs paired into contiguous 2KB
// gmem runs.

static constexpr int B = 16;
static constexpr int H = 128;
static constexpr int W = 128;
static constexpr int C = 256;
static constexpr int P = 8192;
static constexpr int CHUNKS = C / 4;               // 64 float4 per pixel row
static constexpr int ITERS = 8;                    // pipeline iterations
static constexpr int PPB   = ITERS * 4;            // 32 points per block
static constexpr int NBLOCKS = B * P / PPB;        // 4096

__device__ __forceinline__ void cp16(uint32_t dst_smem, const void* src_gmem) {
    asm volatile("cp.async.cg.shared.global [%0], [%1], 16;"
                 :: "r"(dst_smem), "l"(src_gmem));
}
#define CP_COMMIT() asm volatile("cp.async.commit_group;" ::: "memory")
#define CP_WAIT1()  asm volatile("cp.async.wait_group 1;" ::: "memory")
#define CP_WAIT0()  asm volatile("cp.async.wait_group 0;" ::: "memory")

__global__ __launch_bounds__(256, 6)
void grid_nd_sample_kernel(const float* __restrict__ in_tensor,
                           const float2* __restrict__ indices,
                           float4* __restrict__ out)
{
    // [stage parity][point-slot][row][chunk] : 2*4*4*64*16B = 32KB
    __shared__ float4 buf[2][4][4][CHUNKS];
    __shared__ float2 sidx[PPB];

    const unsigned tid   = threadIdx.x;
    const unsigned wid   = tid >> 5;
    const unsigned lane  = tid & 31;
    const unsigned pt4   = wid >> 1;          // point slot 0..3 within a stage
    const unsigned hf    = wid & 1;           // which half of C this warp owns
    const unsigned chunk = hf * 32 + lane;    // float4 chunk 0..63
    const unsigned pbase = blockIdx.x * PPB;

    // Stage the block's 32 indices (one coalesced 256B load).
    if (tid < PPB)
        sidx[tid] = __ldg(&indices[pbase + tid]);
    __syncthreads();

    const float4* base = (const float4*)in_tensor;

    auto issue = [&](int it) {
        int lp = it * 4 + (int)pt4;
        unsigned pidx = pbase + lp;
        unsigned b = pidx >> 13;              // P = 8192 = 2^13
        float2 ind = sidx[lp];
        int h0 = (int)floorf(ind.x);
        int w0 = (int)floorf(ind.y);
        unsigned boff = b * (H * W * CHUNKS);
        unsigned r0 = boff + (h0 * W + w0) * CHUNKS + chunk;   // (h0,w0)
        uint32_t d = (uint32_t)__cvta_generic_to_shared(&buf[it & 1][pt4][0][chunk]);
        const uint32_t ROWB = CHUNKS * 16;    // 1024B per row in buf
        // buf rows: [0]=p1(h0,w0) [1]=p2(h1,w0) [2]=p3(h0,w1) [3]=p4(h1,w1)
        // issue order pairs contiguous 2KB gmem runs: (h0,w0)+(h0,w1), then
        // (h1,w0)+(h1,w1).
        cp16(d + 0 * ROWB, &base[r0]);
        cp16(d + 2 * ROWB, &base[r0 + CHUNKS]);
        cp16(d + 1 * ROWB, &base[r0 + W * CHUNKS]);
        cp16(d + 3 * ROWB, &base[r0 + (W + 1) * CHUNKS]);
    };

    // Prologue: fill both stages.
    issue(0); CP_COMMIT();
    issue(1); CP_COMMIT();

#pragma unroll
    for (int it = 0; it < ITERS; ++it) {
        if (it < ITERS - 1) { CP_WAIT1(); } else { CP_WAIT0(); }

        int lp = it * 4 + (int)pt4;
        unsigned pidx = pbase + lp;
        float2 ind = sidx[lp];
        float mu_h = ind.x - floorf(ind.x);
        float mu_w = ind.y - floorf(ind.y);

        float4 p1 = buf[it & 1][pt4][0][chunk];
        float4 p2 = buf[it & 1][pt4][1][chunk];
        float4 p3 = buf[it & 1][pt4][2][chunk];
        float4 p4 = buf[it & 1][pt4][3][chunk];

        float4 o;
        {
            float a = fmaf(mu_h, p2.x - p1.x, p1.x);
            float c = fmaf(mu_h, p4.x - p3.x, p3.x);
            o.x = fmaf(mu_w, c - a, a);
        }
        {
            float a = fmaf(mu_h, p2.y - p1.y, p1.y);
            float c = fmaf(mu_h, p4.y - p3.y, p3.y);
            o.y = fmaf(mu_w, c - a, a);
        }
        {
            float a = fmaf(mu_h, p2.z - p1.z, p1.z);
            float c = fmaf(mu_h, p4.z - p3.z, p3.z);
            o.z = fmaf(mu_w, c - a, a);
        }
        {
            float a = fmaf(mu_h, p2.w - p1.w, p1.w);
            float c = fmaf(mu_h, p4.w - p3.w, p3.w);
            o.w = fmaf(mu_w, c - a, a);
        }

        __stcs(&out[pidx * (unsigned)CHUNKS + chunk], o);

        if (it + 2 < ITERS) { issue(it + 2); CP_COMMIT(); }
    }
}

extern "C" void kernel_launch(void* const* d_in, const int* in_sizes, int n_in,
                              void* d_out, int out_size)
{
    const float*  in_tensor = (const float*)d_in[0];
    const float2* indices   = (const float2*)d_in[1];
    float4*       out       = (float4*)d_out;

    grid_nd_sample_kernel<<<NBLOCKS, 256>>>(in_tensor, indices, out);
}

// round 13
// speedup vs baseline: 1.1592x; 1.0027x over previous
#include <cuda_runtime.h>
#include <cuda_bf16.h>
#include <cstdint>

// Grid_nd_sample: bilinear interpolation gather — cp.async pipelined.
// in_tensor: (B=16, H=128, W=128, C=256) fp32
// indices:   (B=16, P=8192, 2) fp32  -- coord0 = H axis, coord1 = W axis
// out:       (B, P, C) fp32
//
// R12 structure (best known, 59.9us): 32 points/block, grid=4096, 2-stage
// cp.async pipeline, 6 blocks/SM. 32 pts/block keeps the concurrent wave's
// batch footprint (~56MB) under the 126MB L2 — measured: 64 pts/block
// thrashes (+50MB DRAM). Traffic is at the compulsory floor (~334MB); DRAM
// duty ~77% is the pattern's efficiency ceiling.
// Delta vs R12: mu/pidx carried in registers from issue-time (two parity
// slots, x2-unrolled loop) — removes an LDS + 2 floorf from the body.

static constexpr int B = 16;
static constexpr int H = 128;
static constexpr int W = 128;
static constexpr int C = 256;
static constexpr int P = 8192;
static constexpr int CHUNKS = C / 4;               // 64 float4 per pixel row
static constexpr int ITERS = 8;                    // pipeline iterations (even)
static constexpr int PPB   = ITERS * 4;            // 32 points per block
static constexpr int NBLOCKS = B * P / PPB;        // 4096

__device__ __forceinline__ void cp16(uint32_t dst_smem, const void* src_gmem) {
    asm volatile("cp.async.cg.shared.global [%0], [%1], 16;"
                 :: "r"(dst_smem), "l"(src_gmem));
}
#define CP_COMMIT() asm volatile("cp.async.commit_group;" ::: "memory")
#define CP_WAIT1()  asm volatile("cp.async.wait_group 1;" ::: "memory")
#define CP_WAIT0()  asm volatile("cp.async.wait_group 0;" ::: "memory")

__global__ __launch_bounds__(256, 6)
void grid_nd_sample_kernel(const float* __restrict__ in_tensor,
                           const float2* __restrict__ indices,
                           float4* __restrict__ out)
{
    // [stage parity][point-slot][row][chunk] : 2*4*4*64*16B = 32KB
    __shared__ float4 buf[2][4][4][CHUNKS];
    __shared__ float2 sidx[PPB];

    const unsigned tid   = threadIdx.x;
    const unsigned wid   = tid >> 5;
    const unsigned lane  = tid & 31;
    const unsigned pt4   = wid >> 1;          // point slot 0..3 within a stage
    const unsigned hf    = wid & 1;           // which half of C this warp owns
    const unsigned chunk = hf * 32 + lane;    // float4 chunk 0..63
    const unsigned pbase = blockIdx.x * PPB;

    // Stage the block's 32 indices (one coalesced 256B load).
    if (tid < PPB)
        sidx[tid] = __ldg(&indices[pbase + tid]);
    __syncthreads();

    const float4* base = (const float4*)in_tensor;

    // issue(it): start the 4 row gathers for iteration it into buf[it&1] and
    // hand mu/pidx back in registers so the body never re-touches sidx.
    auto issue = [&](int it, float& omh, float& omw, unsigned& opx) {
        int lp = it * 4 + (int)pt4;
        unsigned pidx = pbase + lp;
        unsigned b = pidx >> 13;              // P = 8192 = 2^13
        float2 ind = sidx[lp];
        float fh = floorf(ind.x);
        float fw = floorf(ind.y);
        int h0 = (int)fh;
        int w0 = (int)fw;
        unsigned boff = b * (H * W * CHUNKS);
        unsigned r0 = boff + (h0 * W + w0) * CHUNKS + chunk;   // (h0,w0)
        uint32_t d = (uint32_t)__cvta_generic_to_shared(&buf[it & 1][pt4][0][chunk]);
        const uint32_t ROWB = CHUNKS * 16;    // 1024B per row in buf
        // buf rows: [0]=p1(h0,w0) [1]=p2(h1,w0) [2]=p3(h0,w1) [3]=p4(h1,w1)
        // issue order pairs contiguous 2KB gmem runs: (h0,w0)+(h0,w1), then
        // (h1,w0)+(h1,w1).  (h1=h0+1, w1=w0+1 is exact: integer coord -> mu=0
        // -> lerp returns p1 bitwise; +1 always in bounds since coords < 127.)
        cp16(d + 0 * ROWB, &base[r0]);
        cp16(d + 2 * ROWB, &base[r0 + CHUNKS]);
        cp16(d + 1 * ROWB, &base[r0 + W * CHUNKS]);
        cp16(d + 3 * ROWB, &base[r0 + (W + 1) * CHUNKS]);
        omh = ind.x - fh;
        omw = ind.y - fw;
        opx = pidx;
    };

    auto body = [&](int it, float& mh_s, float& mw_s, unsigned& px_s) {
        if (it + 1 < ITERS) { CP_WAIT1(); } else { CP_WAIT0(); }

        float4 p1 = buf[it & 1][pt4][0][chunk];
        float4 p2 = buf[it & 1][pt4][1][chunk];
        float4 p3 = buf[it & 1][pt4][2][chunk];
        float4 p4 = buf[it & 1][pt4][3][chunk];

        float mh = mh_s, mw = mw_s;
        unsigned px = px_s;

        float4 o;
        {
            float a = fmaf(mh, p2.x - p1.x, p1.x);
            float c = fmaf(mh, p4.x - p3.x, p3.x);
            o.x = fmaf(mw, c - a, a);
        }
        {
            float a = fmaf(mh, p2.y - p1.y, p1.y);
            float c = fmaf(mh, p4.y - p3.y, p3.y);
            o.y = fmaf(mw, c - a, a);
        }
        {
            float a = fmaf(mh, p2.z - p1.z, p1.z);
            float c = fmaf(mh, p4.z - p3.z, p3.z);
            o.z = fmaf(mw, c - a, a);
        }
        {
            float a = fmaf(mh, p2.w - p1.w, p1.w);
            float c = fmaf(mh, p4.w - p3.w, p3.w);
            o.w = fmaf(mw, c - a, a);
        }

        __stcs(&out[px * (unsigned)CHUNKS + chunk], o);

        if (it + 2 < ITERS) { issue(it + 2, mh_s, mw_s, px_s); CP_COMMIT(); }
    };

    // Register-carried pipeline state, one set per stage parity.
    float mh0, mw0, mh1, mw1;
    unsigned px0, px1;

    issue(0, mh0, mw0, px0); CP_COMMIT();
    issue(1, mh1, mw1, px1); CP_COMMIT();

#pragma unroll
    for (int it = 0; it < ITERS; it += 2) {
        body(it,     mh0, mw0, px0);
        body(it + 1, mh1, mw1, px1);
    }
}

extern "C" void kernel_launch(void* const* d_in, const int* in_sizes, int n_in,
                              void* d_out, int out_size)
{
    const float*  in_tensor = (const float*)d_in[0];
    const float2* indices   = (const float2*)d_in[1];
    float4*       out       = (float4*)d_out;

    grid_nd_sample_kernel<<<NBLOCKS, 256>>>(in_tensor, indices, out);
}

// round 14
// speedup vs baseline: 1.1604x; 1.0011x over previous
#include <cuda_runtime.h>
#include <cuda_bf16.h>
#include <cstdint>

// Grid_nd_sample: bilinear interpolation gather — 3-stage cp.async pipeline.
// in_tensor: (B=16, H=128, W=128, C=256) fp32
// indices:   (B=16, P=8192, 2) fp32  -- coord0 = H axis, coord1 = W axis
// out:       (B, P, C) fp32
//
// Best-known structure (R12/R13, 59.7us): 32 points/block, grid=4096.
// 32 pts/block keeps the concurrent wave's batch footprint (~56MB) under the
// 126MB L2 (64 pts/block thrashes: +50MB DRAM, measured). Traffic is at the
// compulsory floor (~334MB); total L2 throughput (~11.4TB/s) sits at the LTS
// cap, which is why occupancy/MLP knobs don't move DRAM% past ~77%.
// Delta vs R13: pipeline depth 2 -> 3 (48KB smem, 4 blocks/SM) — each warp
// tolerates one extra gather latency of jitter before wait_group stalls.

static constexpr int B = 16;
static constexpr int H = 128;
static constexpr int W = 128;
static constexpr int C = 256;
static constexpr int P = 8192;
static constexpr int CHUNKS = C / 4;               // 64 float4 per pixel row
static constexpr int ITERS = 8;                    // pipeline iterations
static constexpr int STAGES = 3;
static constexpr int PPB   = ITERS * 4;            // 32 points per block
static constexpr int NBLOCKS = B * P / PPB;        // 4096

__device__ __forceinline__ void cp16(uint32_t dst_smem, const void* src_gmem) {
    asm volatile("cp.async.cg.shared.global [%0], [%1], 16;"
                 :: "r"(dst_smem), "l"(src_gmem));
}
#define CP_COMMIT() asm volatile("cp.async.commit_group;" ::: "memory")
#define CP_WAIT2()  asm volatile("cp.async.wait_group 2;" ::: "memory")
#define CP_WAIT1()  asm volatile("cp.async.wait_group 1;" ::: "memory")
#define CP_WAIT0()  asm volatile("cp.async.wait_group 0;" ::: "memory")

__global__ __launch_bounds__(256, 4)
void grid_nd_sample_kernel(const float* __restrict__ in_tensor,
                           const float2* __restrict__ indices,
                           float4* __restrict__ out)
{
    // [stage][point-slot][row][chunk] : 3*4*4*64*16B = 48KB
    __shared__ float4 buf[STAGES][4][4][CHUNKS];
    __shared__ float2 sidx[PPB];

    const unsigned tid   = threadIdx.x;
    const unsigned wid   = tid >> 5;
    const unsigned lane  = tid & 31;
    const unsigned pt4   = wid >> 1;          // point slot 0..3 within a stage
    const unsigned hf    = wid & 1;           // which half of C this warp owns
    const unsigned chunk = hf * 32 + lane;    // float4 chunk 0..63
    const unsigned pbase = blockIdx.x * PPB;

    // Stage the block's 32 indices (one coalesced 256B load).
    if (tid < PPB)
        sidx[tid] = __ldg(&indices[pbase + tid]);
    __syncthreads();

    const float4* base = (const float4*)in_tensor;

    auto issue = [&](int it) {
        int lp = it * 4 + (int)pt4;
        unsigned pidx = pbase + lp;
        unsigned b = pidx >> 13;              // P = 8192 = 2^13
        float2 ind = sidx[lp];
        int h0 = (int)floorf(ind.x);
        int w0 = (int)floorf(ind.y);
        unsigned boff = b * (H * W * CHUNKS);
        unsigned r0 = boff + (h0 * W + w0) * CHUNKS + chunk;   // (h0,w0)
        uint32_t d = (uint32_t)__cvta_generic_to_shared(&buf[it % STAGES][pt4][0][chunk]);
        const uint32_t ROWB = CHUNKS * 16;    // 1024B per row in buf
        // buf rows: [0]=p1(h0,w0) [1]=p2(h1,w0) [2]=p3(h0,w1) [3]=p4(h1,w1)
        // issue order pairs contiguous 2KB gmem runs: (h0,w0)+(h0,w1), then
        // (h1,w0)+(h1,w1).  (h1=h0+1, w1=w0+1 is exact: integer coord -> mu=0
        // -> lerp returns p1 bitwise; +1 always in bounds since coords < 127.)
        cp16(d + 0 * ROWB, &base[r0]);
        cp16(d + 2 * ROWB, &base[r0 + CHUNKS]);
        cp16(d + 1 * ROWB, &base[r0 + W * CHUNKS]);
        cp16(d + 3 * ROWB, &base[r0 + (W + 1) * CHUNKS]);
    };

    // Prologue: fill all three stages.
    issue(0); CP_COMMIT();
    issue(1); CP_COMMIT();
    issue(2); CP_COMMIT();

#pragma unroll
    for (int it = 0; it < ITERS; ++it) {
        // Pending groups after this wait: the stages still in flight.
        if (it + 2 < ITERS)      { CP_WAIT2(); }
        else if (it + 1 < ITERS) { CP_WAIT1(); }
        else                     { CP_WAIT0(); }

        int lp = it * 4 + (int)pt4;
        unsigned pidx = pbase + lp;
        float2 ind = sidx[lp];
        float mu_h = ind.x - floorf(ind.x);
        float mu_w = ind.y - floorf(ind.y);

        float4 p1 = buf[it % STAGES][pt4][0][chunk];
        float4 p2 = buf[it % STAGES][pt4][1][chunk];
        float4 p3 = buf[it % STAGES][pt4][2][chunk];
        float4 p4 = buf[it % STAGES][pt4][3][chunk];

        float4 o;
        {
            float a = fmaf(mu_h, p2.x - p1.x, p1.x);
            float c = fmaf(mu_h, p4.x - p3.x, p3.x);
            o.x = fmaf(mu_w, c - a, a);
        }
        {
            float a = fmaf(mu_h, p2.y - p1.y, p1.y);
            float c = fmaf(mu_h, p4.y - p3.y, p3.y);
            o.y = fmaf(mu_w, c - a, a);
        }
        {
            float a = fmaf(mu_h, p2.z - p1.z, p1.z);
            float c = fmaf(mu_h, p4.z - p3.z, p3.z);
            o.z = fmaf(mu_w, c - a, a);
        }
        {
            float a = fmaf(mu_h, p2.w - p1.w, p1.w);
            float c = fmaf(mu_h, p4.w - p3.w, p3.w);
            o.w = fmaf(mu_w, c - a, a);
        }

        __stcs(&out[pidx * (unsigned)CHUNKS + chunk], o);

        if (it + STAGES < ITERS) { issue(it + STAGES); CP_COMMIT(); }
    }
}

extern "C" void kernel_launch(void* const* d_in, const int* in_sizes, int n_in,
                              void* d_out, int out_size)
{
    const float*  in_tensor = (const float*)d_in[0];
    const float2* indices   = (const float2*)d_in[1];
    float4*       out       = (float4*)d_out;

    grid_nd_sample_kernel<<<NBLOCKS, 256>>>(in_tensor, indices, out);
}